// round 9
// baseline (speedup 1.0000x reference)
#include <cuda_runtime.h>
#include <cuda_bf16.h>
#include <cstdint>

#define BB_ 4
#define LL_ 512
#define HH_ 768
#define HS_ 64
#define OUT_ 16
#define NTOK (BB_*LL_)          // 2048
#define NPAIR ((LL_*(LL_+1))/2) // 131328
#define NSPLIT 6
#define TI_ 8
#define TJ_ 128

__device__ __forceinline__ uint32_t smem_u32(const void* p) {
    return (uint32_t)__cvta_generic_to_shared(p);
}

// ---------------------------------------------------------------------------
// Scratch (static device globals; no allocations allowed)
// ---------------------------------------------------------------------------
__device__ __nv_bfloat16 g_xhi[NTOK * HH_];
__device__ __nv_bfloat16 g_xlo[NTOK * HH_];
__device__ __nv_bfloat16 g_wthi[128 * HH_];   // W transposed: [n][k]
__device__ __nv_bfloat16 g_wtlo[128 * HH_];
__device__ float g_part[NSPLIT][NTOK * 128];
__device__ float g_q[NTOK * HS_];
__device__ float g_k[NTOK * HS_];
__device__ float g_A[NTOK * OUT_];
__device__ float g_C[NTOK * OUT_];

union BF4 { __nv_bfloat16 b[4]; uint2 u; };
union BF8 { __nv_bfloat16 b[8]; uint4 u; };

// ---------------------------------------------------------------------------
// Kernel 0: prep.  Blocks 0..1535: split x into bf16 hi/lo.
//           Blocks 1536..1559: transpose+split W (Wq|Wk) -> Wt[n][k] hi/lo.
// ---------------------------------------------------------------------------
__global__ __launch_bounds__(256) void prep_kernel(
    const float* __restrict__ x,
    const float* __restrict__ Wq, const float* __restrict__ Wk)
{
    __shared__ float Sm[128][33];
    const int tid = threadIdx.x;

    if (blockIdx.x < 1536) {
        const int e = blockIdx.x * 256 + tid;       // float4 index
        float4 v = ((const float4*)x)[e];
        float f[4] = {v.x, v.y, v.z, v.w};
        BF4 hi, lo;
        #pragma unroll
        for (int i = 0; i < 4; i++) {
            hi.b[i] = __float2bfloat16(f[i]);
            lo.b[i] = __float2bfloat16(f[i] - __bfloat162float(hi.b[i]));
        }
        *(uint2*)(g_xhi + 4 * (size_t)e) = hi.u;
        *(uint2*)(g_xlo + 4 * (size_t)e) = lo.u;
    } else {
        const int k0 = (blockIdx.x - 1536) * 32;
        #pragma unroll
        for (int it = 0; it < 16; it++) {
            int e = tid + 256 * it;
            int k = e >> 7, n = e & 127;
            float w = (n < 64) ? Wq[(size_t)(k0 + k) * 64 + n]
                               : Wk[(size_t)(k0 + k) * 64 + (n - 64)];
            Sm[n][k] = w;
        }
        __syncthreads();
        const int n = tid >> 1;
        const int h = (tid & 1) * 16;
        BF8 hbuf[2], lbuf[2];
        #pragma unroll
        for (int j = 0; j < 16; j++) {
            float w = Sm[n][h + j];
            __nv_bfloat16 whi = __float2bfloat16(w);
            __nv_bfloat16 wlo = __float2bfloat16(w - __bfloat162float(whi));
            hbuf[j >> 3].b[j & 7] = whi;
            lbuf[j >> 3].b[j & 7] = wlo;
        }
        const size_t off = (size_t)n * HH_ + k0 + h;
        *(uint4*)(g_wthi + off)     = hbuf[0].u;
        *(uint4*)(g_wthi + off + 8) = hbuf[1].u;
        *(uint4*)(g_wtlo + off)     = lbuf[0].u;
        *(uint4*)(g_wtlo + off + 8) = lbuf[1].u;
    }
}

// ---------------------------------------------------------------------------
// Kernel 1: mma.sync projection.  D[128m][128n] = A[128][K] * B[128][K]^T,
// bf16-split (hi*hi + hi*lo + lo*hi), eff K = 3*768, split-K=6 slices of 384.
// Grid (16, 6), 256 threads (8 warps of 32x64).  SMEM tiles in 8x8-subtile
// blocked layout: subtile(rt, kt) at ((rt*4+kt)*128) bytes, 8 rows x 16B.
// ldmatrix.x4 per fragment group -> conflict-free 128B reads.
// ---------------------------------------------------------------------------
#define PM_CHUNKS 12

__global__ __launch_bounds__(256) void proj_mma_kernel()
{
    __shared__ __align__(128) char As[2][8192];
    __shared__ __align__(128) char Bs[2][8192];

    const int tid  = threadIdx.x;
    const int lane = tid & 31;
    const int warp = tid >> 5;

    const int m0 = blockIdx.x * 128;
    const int s  = blockIdx.y;
    const int region = s >> 1;              // 0: hi*hi, 1: hi*lo, 2: lo*hi
    const int kbase  = (s & 1) * 384;
    const __nv_bfloat16* xa = (region == 2) ? g_xlo : g_xhi;
    const __nv_bfloat16* wa = (region == 1) ? g_wtlo : g_wthi;

    const int mw = (warp >> 1) * 32;        // 0,32,64,96
    const int nw = (warp & 1) * 64;         // 0,64

    float d[2][8][4];
    #pragma unroll
    for (int a = 0; a < 2; a++)
        #pragma unroll
        for (int b = 0; b < 8; b++)
            #pragma unroll
            for (int r = 0; r < 4; r++) d[a][b][r] = 0.f;

    // Staging mapping: idx = tid + 256*e (0..511): row = idx>>2, kt = idx&3.
    float4 ra[2], rb[2];

    // LDG chunk 0
    #pragma unroll
    for (int e = 0; e < 2; e++) {
        const int idx = tid + 256 * e;
        const int row = idx >> 2, kt = idx & 3;
        ra[e] = *(const float4*)(xa + (size_t)(m0 + row) * HH_ + kbase + kt * 8);
        rb[e] = *(const float4*)(wa + (size_t)row * HH_ + kbase + kt * 8);
    }
    // STS chunk 0 -> buffer 0
    #pragma unroll
    for (int e = 0; e < 2; e++) {
        const int idx = tid + 256 * e;
        const int row = idx >> 2, kt = idx & 3;
        const int off = ((row >> 3) * 4 + kt) * 128 + (row & 7) * 16;
        *(float4*)(As[0] + off) = ra[e];
        *(float4*)(Bs[0] + off) = rb[e];
    }
    __syncthreads();

    for (int c = 0; c < PM_CHUNKS; c++) {
        const int buf = c & 1;

        if (c + 1 < PM_CHUNKS) {
            const int k0 = kbase + (c + 1) * 32;
            #pragma unroll
            for (int e = 0; e < 2; e++) {
                const int idx = tid + 256 * e;
                const int row = idx >> 2, kt = idx & 3;
                ra[e] = *(const float4*)(xa + (size_t)(m0 + row) * HH_ + k0 + kt * 8);
                rb[e] = *(const float4*)(wa + (size_t)row * HH_ + k0 + kt * 8);
            }
        }

        const uint32_t abase = smem_u32(As[buf]);
        const uint32_t bbase = smem_u32(Bs[buf]);
        const int g = lane >> 3;            // ldmatrix address group

        #pragma unroll
        for (int ks = 0; ks < 2; ks++) {
            const int kt0 = ks * 2;

            // A fragments: 2 m16k16 tiles
            uint32_t afr[2][4];
            #pragma unroll
            for (int mt2 = 0; mt2 < 2; mt2++) {
                const int mt = (mw >> 3) + mt2 * 2;
                const uint32_t addr = abase +
                    (uint32_t)((((mt + (g & 1)) * 4) + kt0 + (g >> 1)) * 128 + (lane & 7) * 16);
                asm volatile(
                    "ldmatrix.sync.aligned.m8n8.x4.shared.b16 {%0,%1,%2,%3}, [%4];"
                    : "=r"(afr[mt2][0]), "=r"(afr[mt2][1]),
                      "=r"(afr[mt2][2]), "=r"(afr[mt2][3])
                    : "r"(addr));
            }

            // B fragments: 8 k16n8 tiles, fetched 2 at a time via x4
            uint32_t bfr[8][2];
            #pragma unroll
            for (int j = 0; j < 4; j++) {
                const int nt = (nw >> 3) + j * 2;
                const uint32_t addr = bbase +
                    (uint32_t)((((nt + (g >> 1)) * 4) + kt0 + (g & 1)) * 128 + (lane & 7) * 16);
                uint32_t q0, q1, q2, q3;
                asm volatile(
                    "ldmatrix.sync.aligned.m8n8.x4.shared.b16 {%0,%1,%2,%3}, [%4];"
                    : "=r"(q0), "=r"(q1), "=r"(q2), "=r"(q3)
                    : "r"(addr));
                bfr[2*j][0] = q0; bfr[2*j][1] = q1;
                bfr[2*j+1][0] = q2; bfr[2*j+1][1] = q3;
            }

            #pragma unroll
            for (int mt2 = 0; mt2 < 2; mt2++)
                #pragma unroll
                for (int nt = 0; nt < 8; nt++) {
                    asm volatile(
                        "mma.sync.aligned.m16n8k16.row.col.f32.bf16.bf16.f32 "
                        "{%0,%1,%2,%3}, {%4,%5,%6,%7}, {%8,%9}, {%0,%1,%2,%3};"
                        : "+f"(d[mt2][nt][0]), "+f"(d[mt2][nt][1]),
                          "+f"(d[mt2][nt][2]), "+f"(d[mt2][nt][3])
                        : "r"(afr[mt2][0]), "r"(afr[mt2][1]),
                          "r"(afr[mt2][2]), "r"(afr[mt2][3]),
                          "r"(bfr[nt][0]),  "r"(bfr[nt][1]));
                }
        }

        if (c + 1 < PM_CHUNKS) {
            const int nxt = 1 - buf;
            #pragma unroll
            for (int e = 0; e < 2; e++) {
                const int idx = tid + 256 * e;
                const int row = idx >> 2, kt = idx & 3;
                const int off = ((row >> 3) * 4 + kt) * 128 + (row & 7) * 16;
                *(float4*)(As[nxt] + off) = ra[e];
                *(float4*)(Bs[nxt] + off) = rb[e];
            }
            __syncthreads();
        }
    }

    // Epilogue: store partials.  d frag: {d0,d1}=(row, col..col+1), {d2,d3}=(row+8).
    float* dst = g_part[s];
    const int rrow = lane >> 2;
    const int ccol = (lane & 3) * 2;
    #pragma unroll
    for (int mt2 = 0; mt2 < 2; mt2++)
        #pragma unroll
        for (int nt = 0; nt < 8; nt++) {
            const int m   = m0 + mw + mt2 * 16 + rrow;
            const int col = nw + nt * 8 + ccol;
            *(float2*)(dst + (size_t)m * 128 + col) =
                make_float2(d[mt2][nt][0], d[mt2][nt][1]);
            *(float2*)(dst + (size_t)(m + 8) * 128 + col) =
                make_float2(d[mt2][nt][2], d[mt2][nt][3]);
        }
}

// ---------------------------------------------------------------------------
// Kernel 2: combine 6 split-K partials + bias -> g_q/g_k, then fused A/C.
// ---------------------------------------------------------------------------
__global__ __launch_bounds__(256) void combine_kernel(
    const float* __restrict__ bq, const float* __restrict__ bk,
    const float* __restrict__ Wb, const float* __restrict__ bb)
{
    __shared__ __align__(16) float S[16][128];
    __shared__ __align__(16) float WBs[256 * 16];

    const int tid = threadIdx.x;
    const int m0  = blockIdx.x * 16;

    {
        const float4* src = (const float4*)Wb;
        float4* dst = (float4*)WBs;
        #pragma unroll
        for (int t = 0; t < 4; t++) dst[tid + 256 * t] = src[tid + 256 * t];
    }

    const size_t base4 = (size_t)m0 * 32;
    #pragma unroll
    for (int e = 0; e < 2; e++) {
        const int idx = tid + 256 * e;
        const int m   = idx >> 5;
        const int n   = (idx & 31) * 4;
        float4 v = ((const float4*)g_part[0])[base4 + idx];
        #pragma unroll
        for (int s = 1; s < NSPLIT; s++) {
            float4 p = ((const float4*)g_part[s])[base4 + idx];
            v.x += p.x; v.y += p.y; v.z += p.z; v.w += p.w;
        }
        float4 bias = (n < 64) ? *(const float4*)(bq + n)
                               : *(const float4*)(bk + (n - 64));
        v.x += bias.x; v.y += bias.y; v.z += bias.z; v.w += bias.w;
        if (n < 64) *(float4*)(g_q + (size_t)(m0 + m) * HS_ + n)        = v;
        else        *(float4*)(g_k + (size_t)(m0 + m) * HS_ + (n - 64)) = v;
        *(float4*)(&S[m][n]) = v;
    }
    __syncthreads();

    {
        const int am = tid >> 4;
        const int ao = tid & 15;
        const float* Sr = &S[am][0];
        float a = 0.f;
        float c = bb[ao];
        #pragma unroll
        for (int h = 0; h < HS_; h++) {
            float qv = Sr[h];
            float kv = Sr[64 + h];
            a += qv * WBs[h * 16 + ao];
            c += qv * WBs[(128 + h) * 16 + ao];
            c += kv * (WBs[(64 + h) * 16 + ao] + WBs[(192 + h) * 16 + ao]);
        }
        g_A[(m0 + am) * OUT_ + ao] = a;
        g_C[(m0 + am) * OUT_ + ao] = c;
    }
}

// ---------------------------------------------------------------------------
// Kernel 3: tiled pair kernel (round-7 winner, unchanged).
// ---------------------------------------------------------------------------
__global__ __launch_bounds__(256) void pair_kernel(float* __restrict__ out)
{
    __shared__ __align__(16) float4 ks4[TJ_][16];   // 32 KB (rotated cols)
    __shared__ __align__(16) float4 C4s[TJ_ * 4];   // 8 KB
    __shared__ __align__(16) float4 qs4[TI_ * 16];  // 2 KB
    __shared__ __align__(16) float4 A4s[TI_ * 4];   // 512 B
    __shared__ float Sd[TI_][TJ_];                  // 4 KB

    const int b   = blockIdx.y;
    const int tid = threadIdx.x;

    int id = blockIdx.x;
    int g, local;
    if      (id < 64)  { g = 0; local = id; }
    else if (id < 112) { g = 1; local = id - 64; }
    else if (id < 144) { g = 2; local = id - 112; }
    else               { g = 3; local = id - 144; }
    const int per = 4 - g;
    const int i0b = 16 * g + local / per;
    const int jt  = local % per;
    const int i0  = i0b * TI_;
    const int j0  = (g + jt) * TJ_;

    const float4* kg = (const float4*)(g_k + (size_t)(b * LL_ + j0) * HS_);
    #pragma unroll
    for (int e = 0; e < 8; e++) {
        const int idx = tid + 256 * e;
        const int r = idx >> 4, c = idx & 15;
        ks4[r][(c + r) & 15] = kg[idx];
    }
    const float4* cg = (const float4*)(g_C + (size_t)(b * LL_ + j0) * OUT_);
    C4s[tid]       = cg[tid];
    C4s[tid + 256] = cg[tid + 256];
    if (tid < 128) qs4[tid] = ((const float4*)(g_q + (size_t)(b * LL_ + i0) * HS_))[tid];
    if (tid < 32)  A4s[tid] = ((const float4*)(g_A + (size_t)(b * LL_ + i0) * OUT_))[tid];
    __syncthreads();

    {
        const int jj2 = tid & 63;
        const int ii2 = tid >> 6;
        const int ra = jj2, rb = jj2 + 64;

        float4 d00 = make_float4(0,0,0,0), d01 = d00, d10 = d00, d11 = d00;
        #pragma unroll
        for (int c = 0; c < 16; c++) {
            float4 ka = ks4[ra][(c + ra) & 15];
            float4 kb = ks4[rb][(c + rb) & 15];
            float4 qa = qs4[(2 * ii2 + 0) * 16 + c];
            float4 qb = qs4[(2 * ii2 + 1) * 16 + c];
            d00.x += qa.x*ka.x; d00.y += qa.y*ka.y; d00.z += qa.z*ka.z; d00.w += qa.w*ka.w;
            d01.x += qa.x*kb.x; d01.y += qa.y*kb.y; d01.z += qa.z*kb.z; d01.w += qa.w*kb.w;
            d10.x += qb.x*ka.x; d10.y += qb.y*ka.y; d10.z += qb.z*ka.z; d10.w += qb.w*ka.w;
            d11.x += qb.x*kb.x; d11.y += qb.y*kb.y; d11.z += qb.z*kb.z; d11.w += qb.w*kb.w;
        }
        Sd[2*ii2+0][ra] = (d00.x + d00.y) + (d00.z + d00.w);
        Sd[2*ii2+0][rb] = (d01.x + d01.y) + (d01.z + d01.w);
        Sd[2*ii2+1][ra] = (d10.x + d10.y) + (d10.z + d10.w);
        Sd[2*ii2+1][rb] = (d11.x + d11.y) + (d11.z + d11.w);
    }
    __syncthreads();

    {
        const int ii   = tid >> 5;
        const int lane = tid & 31;
        const int i    = i0 + ii;
        const int poff = i * LL_ - (i * (i - 1)) / 2;
        const int o4   = lane & 3;
        const float4 av = A4s[ii * 4 + o4];
        float4* ob = (float4*)out + ((size_t)b * NPAIR + poff + (j0 - i)) * 4;

        #pragma unroll
        for (int it = 0; it < 16; it++) {
            const int idx  = lane + 32 * it;
            const int pair = idx >> 2;
            if (j0 + pair >= i) {
                const float dot = Sd[ii][pair];
                const float4 cv = C4s[idx];
                float4 r;
                r.x = dot + av.x + cv.x;
                r.y = dot + av.y + cv.y;
                r.z = dot + av.z + cv.z;
                r.w = dot + av.w + cv.w;
                ob[idx] = r;
            }
        }
    }
}

// ---------------------------------------------------------------------------
extern "C" void kernel_launch(void* const* d_in, const int* in_sizes, int n_in,
                              void* d_out, int out_size)
{
    const float* x  = (const float*)d_in[0];
    const float* Wq = (const float*)d_in[1];
    const float* bq = (const float*)d_in[2];
    const float* Wk = (const float*)d_in[3];
    const float* bk = (const float*)d_in[4];
    const float* Wb = (const float*)d_in[5];
    const float* bb = (const float*)d_in[6];
    float* out = (float*)d_out;

    prep_kernel<<<1560, 256>>>(x, Wq, Wk);
    proj_mma_kernel<<<dim3(16, 6), 256>>>();
    combine_kernel<<<NTOK / 16, 256>>>(bq, bk, Wb, bb);
    pair_kernel<<<dim3(160, BB_), 256>>>(out);
}

// round 10
// speedup vs baseline: 1.0121x; 1.0121x over previous
#include <cuda_runtime.h>
#include <cuda_bf16.h>
#include <cstdint>

#define BB_ 4
#define LL_ 512
#define HH_ 768
#define HS_ 64
#define OUT_ 16
#define NTOK (BB_*LL_)          // 2048
#define NPAIR ((LL_*(LL_+1))/2) // 131328
#define NSPLIT 6
#define TI_ 8
#define TJ_ 128
#define PM_CHUNKS 12

typedef unsigned long long ull;

__device__ __forceinline__ uint32_t smem_u32(const void* p) {
    return (uint32_t)__cvta_generic_to_shared(p);
}
__device__ __forceinline__ void fma2(ull& d, ull a, ull b) {
    asm("fma.rn.f32x2 %0, %1, %2, %0;" : "+l"(d) : "l"(a), "l"(b));
}
__device__ __forceinline__ float2 un2(ull v) {
    float2 f; asm("mov.b64 {%0, %1}, %2;" : "=f"(f.x), "=f"(f.y) : "l"(v)); return f;
}

// ---------------------------------------------------------------------------
// Scratch (static device globals; no allocations allowed)
// ---------------------------------------------------------------------------
__device__ __nv_bfloat16 g_xhi[NTOK * HH_];
__device__ __nv_bfloat16 g_xlo[NTOK * HH_];
__device__ __nv_bfloat16 g_wthi[128 * HH_];   // W transposed: [n][k]
__device__ __nv_bfloat16 g_wtlo[128 * HH_];
__device__ float g_part[NSPLIT][NTOK * 128];
__device__ float g_q[NTOK * HS_];
__device__ float g_k[NTOK * HS_];
__device__ float g_A[NTOK * OUT_];
__device__ float g_C[NTOK * OUT_];

union BF4 { __nv_bfloat16 b[4]; uint2 u; };
union BF8 { __nv_bfloat16 b[8]; uint4 u; };
union F4U { float4 f; ull u[2]; };

// ---------------------------------------------------------------------------
// Kernel 0: prep.  Blocks 0..1535: split x into bf16 hi/lo.
//           Blocks 1536..1559: transpose+split W (Wq|Wk) -> Wt[n][k] hi/lo.
// ---------------------------------------------------------------------------
__global__ __launch_bounds__(256) void prep_kernel(
    const float* __restrict__ x,
    const float* __restrict__ Wq, const float* __restrict__ Wk)
{
    __shared__ float Sm[128][33];
    const int tid = threadIdx.x;

    if (blockIdx.x < 1536) {
        const int e = blockIdx.x * 256 + tid;       // float4 index
        float4 v = ((const float4*)x)[e];
        float f[4] = {v.x, v.y, v.z, v.w};
        BF4 hi, lo;
        #pragma unroll
        for (int i = 0; i < 4; i++) {
            hi.b[i] = __float2bfloat16(f[i]);
            lo.b[i] = __float2bfloat16(f[i] - __bfloat162float(hi.b[i]));
        }
        *(uint2*)(g_xhi + 4 * (size_t)e) = hi.u;
        *(uint2*)(g_xlo + 4 * (size_t)e) = lo.u;
    } else {
        const int k0 = (blockIdx.x - 1536) * 32;
        #pragma unroll
        for (int it = 0; it < 16; it++) {
            int e = tid + 256 * it;
            int k = e >> 7, n = e & 127;
            float w = (n < 64) ? Wq[(size_t)(k0 + k) * 64 + n]
                               : Wk[(size_t)(k0 + k) * 64 + (n - 64)];
            Sm[n][k] = w;
        }
        __syncthreads();
        const int n = tid >> 1;
        const int h = (tid & 1) * 16;
        BF8 hbuf[2], lbuf[2];
        #pragma unroll
        for (int j = 0; j < 16; j++) {
            float w = Sm[n][h + j];
            __nv_bfloat16 whi = __float2bfloat16(w);
            __nv_bfloat16 wlo = __float2bfloat16(w - __bfloat162float(whi));
            hbuf[j >> 3].b[j & 7] = whi;
            lbuf[j >> 3].b[j & 7] = wlo;
        }
        const size_t off = (size_t)n * HH_ + k0 + h;
        *(uint4*)(g_wthi + off)     = hbuf[0].u;
        *(uint4*)(g_wthi + off + 8) = hbuf[1].u;
        *(uint4*)(g_wtlo + off)     = lbuf[0].u;
        *(uint4*)(g_wtlo + off + 8) = lbuf[1].u;
    }
}

// ---------------------------------------------------------------------------
// Kernel 1: mma.sync projection.  BM=64 now -> grid (32, 6) = 192 blocks.
// D[64m][128n] = A[64][K] * B[128][K]^T per slice, bf16-split, K=384/slice.
// 8 warps: warp tile 16m x 64n (1 m16k16 A-frag x 8 k16n8 B-frags).
// SMEM 8x8-subtile blocked layout; ldmatrix.x4 conflict-free.
// ---------------------------------------------------------------------------
__global__ __launch_bounds__(256) void proj_mma_kernel()
{
    __shared__ __align__(128) char As[2][4096];
    __shared__ __align__(128) char Bs[2][8192];

    const int tid  = threadIdx.x;
    const int lane = tid & 31;
    const int warp = tid >> 5;

    const int m0 = blockIdx.x * 64;
    const int s  = blockIdx.y;
    const int region = s >> 1;              // 0: hi*hi, 1: hi*lo, 2: lo*hi
    const int kbase  = (s & 1) * 384;
    const __nv_bfloat16* xa = (region == 2) ? g_xlo : g_xhi;
    const __nv_bfloat16* wa = (region == 1) ? g_wtlo : g_wthi;

    const int mw = (warp >> 1) * 16;        // 0,16,32,48
    const int nw = (warp & 1) * 64;         // 0,64

    float d[8][4];
    #pragma unroll
    for (int b = 0; b < 8; b++)
        #pragma unroll
        for (int r = 0; r < 4; r++) d[b][r] = 0.f;

    // A staging: 256 float4 (row = tid>>2, kt = tid&3)
    // B staging: 512 float4 (idx = tid+256e, row = idx>>2, kt = idx&3)
    float4 ra, rb[2];

    {
        const int arow = tid >> 2, akt = tid & 3;
        ra = *(const float4*)(xa + (size_t)(m0 + arow) * HH_ + kbase + akt * 8);
        #pragma unroll
        for (int e = 0; e < 2; e++) {
            const int idx = tid + 256 * e;
            const int row = idx >> 2, kt = idx & 3;
            rb[e] = *(const float4*)(wa + (size_t)row * HH_ + kbase + kt * 8);
        }
        const int aoff = ((arow >> 3) * 4 + akt) * 128 + (arow & 7) * 16;
        *(float4*)(As[0] + aoff) = ra;
        #pragma unroll
        for (int e = 0; e < 2; e++) {
            const int idx = tid + 256 * e;
            const int row = idx >> 2, kt = idx & 3;
            const int off = ((row >> 3) * 4 + kt) * 128 + (row & 7) * 16;
            *(float4*)(Bs[0] + off) = rb[e];
        }
    }
    __syncthreads();

    for (int c = 0; c < PM_CHUNKS; c++) {
        const int buf = c & 1;

        if (c + 1 < PM_CHUNKS) {
            const int k0 = kbase + (c + 1) * 32;
            const int arow = tid >> 2, akt = tid & 3;
            ra = *(const float4*)(xa + (size_t)(m0 + arow) * HH_ + k0 + akt * 8);
            #pragma unroll
            for (int e = 0; e < 2; e++) {
                const int idx = tid + 256 * e;
                const int row = idx >> 2, kt = idx & 3;
                rb[e] = *(const float4*)(wa + (size_t)row * HH_ + k0 + kt * 8);
            }
        }

        const uint32_t abase = smem_u32(As[buf]);
        const uint32_t bbase = smem_u32(Bs[buf]);
        const int g = lane >> 3;

        #pragma unroll
        for (int ks = 0; ks < 2; ks++) {
            const int kt0 = ks * 2;

            // A fragment: 1 m16k16 tile
            uint32_t afr[4];
            {
                const int mt = (mw >> 3);
                const uint32_t addr = abase +
                    (uint32_t)((((mt + (g & 1)) * 4) + kt0 + (g >> 1)) * 128 + (lane & 7) * 16);
                asm volatile(
                    "ldmatrix.sync.aligned.m8n8.x4.shared.b16 {%0,%1,%2,%3}, [%4];"
                    : "=r"(afr[0]), "=r"(afr[1]), "=r"(afr[2]), "=r"(afr[3])
                    : "r"(addr));
            }

            // B fragments: 8 k16n8 tiles (2 per x4)
            uint32_t bfr[8][2];
            #pragma unroll
            for (int j = 0; j < 4; j++) {
                const int nt = (nw >> 3) + j * 2;
                const uint32_t addr = bbase +
                    (uint32_t)((((nt + (g >> 1)) * 4) + kt0 + (g & 1)) * 128 + (lane & 7) * 16);
                uint32_t q0, q1, q2, q3;
                asm volatile(
                    "ldmatrix.sync.aligned.m8n8.x4.shared.b16 {%0,%1,%2,%3}, [%4];"
                    : "=r"(q0), "=r"(q1), "=r"(q2), "=r"(q3)
                    : "r"(addr));
                bfr[2*j][0] = q0;   bfr[2*j][1] = q1;
                bfr[2*j+1][0] = q2; bfr[2*j+1][1] = q3;
            }

            #pragma unroll
            for (int nt = 0; nt < 8; nt++) {
                asm volatile(
                    "mma.sync.aligned.m16n8k16.row.col.f32.bf16.bf16.f32 "
                    "{%0,%1,%2,%3}, {%4,%5,%6,%7}, {%8,%9}, {%0,%1,%2,%3};"
                    : "+f"(d[nt][0]), "+f"(d[nt][1]),
                      "+f"(d[nt][2]), "+f"(d[nt][3])
                    : "r"(afr[0]), "r"(afr[1]), "r"(afr[2]), "r"(afr[3]),
                      "r"(bfr[nt][0]), "r"(bfr[nt][1]));
            }
        }

        if (c + 1 < PM_CHUNKS) {
            const int nxt = 1 - buf;
            const int arow = tid >> 2, akt = tid & 3;
            const int aoff = ((arow >> 3) * 4 + akt) * 128 + (arow & 7) * 16;
            *(float4*)(As[nxt] + aoff) = ra;
            #pragma unroll
            for (int e = 0; e < 2; e++) {
                const int idx = tid + 256 * e;
                const int row = idx >> 2, kt = idx & 3;
                const int off = ((row >> 3) * 4 + kt) * 128 + (row & 7) * 16;
                *(float4*)(Bs[nxt] + off) = rb[e];
            }
            __syncthreads();
        }
    }

    // Epilogue: store partials
    float* dst = g_part[s];
    const int rrow = lane >> 2;
    const int ccol = (lane & 3) * 2;
    #pragma unroll
    for (int nt = 0; nt < 8; nt++) {
        const int m   = m0 + mw + rrow;
        const int col = nw + nt * 8 + ccol;
        *(float2*)(dst + (size_t)m * 128 + col) = make_float2(d[nt][0], d[nt][1]);
        *(float2*)(dst + (size_t)(m + 8) * 128 + col) = make_float2(d[nt][2], d[nt][3]);
    }
}

// ---------------------------------------------------------------------------
// Kernel 2: combine 6 split-K partials + bias -> g_q/g_k, then fused A/C.
// ---------------------------------------------------------------------------
__global__ __launch_bounds__(256) void combine_kernel(
    const float* __restrict__ bq, const float* __restrict__ bk,
    const float* __restrict__ Wb, const float* __restrict__ bb)
{
    __shared__ __align__(16) float S[16][128];
    __shared__ __align__(16) float WBs[256 * 16];

    const int tid = threadIdx.x;
    const int m0  = blockIdx.x * 16;

    {
        const float4* src = (const float4*)Wb;
        float4* dst = (float4*)WBs;
        #pragma unroll
        for (int t = 0; t < 4; t++) dst[tid + 256 * t] = src[tid + 256 * t];
    }

    const size_t base4 = (size_t)m0 * 32;
    #pragma unroll
    for (int e = 0; e < 2; e++) {
        const int idx = tid + 256 * e;
        const int m   = idx >> 5;
        const int n   = (idx & 31) * 4;
        float4 v = ((const float4*)g_part[0])[base4 + idx];
        #pragma unroll
        for (int s = 1; s < NSPLIT; s++) {
            float4 p = ((const float4*)g_part[s])[base4 + idx];
            v.x += p.x; v.y += p.y; v.z += p.z; v.w += p.w;
        }
        float4 bias = (n < 64) ? *(const float4*)(bq + n)
                               : *(const float4*)(bk + (n - 64));
        v.x += bias.x; v.y += bias.y; v.z += bias.z; v.w += bias.w;
        if (n < 64) *(float4*)(g_q + (size_t)(m0 + m) * HS_ + n)        = v;
        else        *(float4*)(g_k + (size_t)(m0 + m) * HS_ + (n - 64)) = v;
        *(float4*)(&S[m][n]) = v;
    }
    __syncthreads();

    {
        const int am = tid >> 4;
        const int ao = tid & 15;
        const float* Sr = &S[am][0];
        float a = 0.f;
        float c = bb[ao];
        #pragma unroll
        for (int h = 0; h < HS_; h++) {
            float qv = Sr[h];
            float kv = Sr[64 + h];
            a += qv * WBs[h * 16 + ao];
            c += qv * WBs[(128 + h) * 16 + ao];
            c += kv * (WBs[(64 + h) * 16 + ao] + WBs[(192 + h) * 16 + ao]);
        }
        g_A[(m0 + am) * OUT_ + ao] = a;
        g_C[(m0 + am) * OUT_ + ao] = c;
    }
}

// ---------------------------------------------------------------------------
// Kernel 3: tiled pair kernel.  Transposed k layout ksT[c][j^c]:
//  - staging STS conflict-free (phase banks 4*((j mod 8) xor c))
//  - compute LDS conflict-free (32 lanes -> 32 contiguous 16B slots)
// FFMA2 packed accumulation.  Store phase unchanged (coalesced 512B STG).
// ---------------------------------------------------------------------------
__global__ __launch_bounds__(256) void pair_kernel(float* __restrict__ out)
{
    __shared__ __align__(16) float4 ksT[16][TJ_];   // 32 KB [c][j^c]
    __shared__ __align__(16) float4 C4s[TJ_ * 4];   // 8 KB
    __shared__ __align__(16) float4 qs4[TI_ * 16];  // 2 KB
    __shared__ __align__(16) float4 A4s[TI_ * 4];   // 512 B
    __shared__ float Sd[TI_][TJ_];                  // 4 KB

    const int b   = blockIdx.y;
    const int tid = threadIdx.x;

    int id = blockIdx.x;
    int g, local;
    if      (id < 64)  { g = 0; local = id; }
    else if (id < 112) { g = 1; local = id - 64; }
    else if (id < 144) { g = 2; local = id - 112; }
    else               { g = 3; local = id - 144; }
    const int per = 4 - g;
    const int i0b = 16 * g + local / per;
    const int jt  = local % per;
    const int i0  = i0b * TI_;
    const int j0  = (g + jt) * TJ_;

    // ---- Stage tiles ----
    const float4* kg = (const float4*)(g_k + (size_t)(b * LL_ + j0) * HS_);
    #pragma unroll
    for (int e = 0; e < 8; e++) {
        const int idx = tid + 256 * e;
        const int j = idx >> 4, c = idx & 15;
        ksT[c][j ^ c] = kg[idx];
    }
    const float4* cg = (const float4*)(g_C + (size_t)(b * LL_ + j0) * OUT_);
    C4s[tid]       = cg[tid];
    C4s[tid + 256] = cg[tid + 256];
    if (tid < 128) qs4[tid] = ((const float4*)(g_q + (size_t)(b * LL_ + i0) * HS_))[tid];
    if (tid < 32)  A4s[tid] = ((const float4*)(g_A + (size_t)(b * LL_ + i0) * OUT_))[tid];
    __syncthreads();

    // ---- Compute S[8][128]: thread -> rows {2ii2, 2ii2+1}, cols {ra, rb} ----
    {
        const int jj2 = tid & 63;
        const int ii2 = tid >> 6;
        const int ra = jj2, rb = jj2 + 64;

        ull a00[2] = {0,0}, a01[2] = {0,0}, a10[2] = {0,0}, a11[2] = {0,0};
        #pragma unroll
        for (int c = 0; c < 16; c++) {
            F4U ka, kb, qa, qb;
            ka.f = ksT[c][ra ^ c];
            kb.f = ksT[c][rb ^ c];
            qa.f = qs4[(2 * ii2 + 0) * 16 + c];
            qb.f = qs4[(2 * ii2 + 1) * 16 + c];
            fma2(a00[0], qa.u[0], ka.u[0]); fma2(a00[1], qa.u[1], ka.u[1]);
            fma2(a01[0], qa.u[0], kb.u[0]); fma2(a01[1], qa.u[1], kb.u[1]);
            fma2(a10[0], qb.u[0], ka.u[0]); fma2(a10[1], qb.u[1], ka.u[1]);
            fma2(a11[0], qb.u[0], kb.u[0]); fma2(a11[1], qb.u[1], kb.u[1]);
        }
        float2 r0, r1;
        r0 = un2(a00[0]); r1 = un2(a00[1]);
        Sd[2*ii2+0][ra] = (r0.x + r0.y) + (r1.x + r1.y);
        r0 = un2(a01[0]); r1 = un2(a01[1]);
        Sd[2*ii2+0][rb] = (r0.x + r0.y) + (r1.x + r1.y);
        r0 = un2(a10[0]); r1 = un2(a10[1]);
        Sd[2*ii2+1][ra] = (r0.x + r0.y) + (r1.x + r1.y);
        r0 = un2(a11[0]); r1 = un2(a11[1]);
        Sd[2*ii2+1][rb] = (r0.x + r0.y) + (r1.x + r1.y);
    }
    __syncthreads();

    // ---- Store phase: warp -> row ii; lanes write consecutive float4 ----
    {
        const int ii   = tid >> 5;
        const int lane = tid & 31;
        const int i    = i0 + ii;
        const int poff = i * LL_ - (i * (i - 1)) / 2;
        const int o4   = lane & 3;
        const float4 av = A4s[ii * 4 + o4];
        float4* ob = (float4*)out + ((size_t)b * NPAIR + poff + (j0 - i)) * 4;

        #pragma unroll
        for (int it = 0; it < 16; it++) {
            const int idx  = lane + 32 * it;
            const int pair = idx >> 2;
            if (j0 + pair >= i) {
                const float dot = Sd[ii][pair];
                const float4 cv = C4s[idx];
                float4 r;
                r.x = dot + av.x + cv.x;
                r.y = dot + av.y + cv.y;
                r.z = dot + av.z + cv.z;
                r.w = dot + av.w + cv.w;
                ob[idx] = r;
            }
        }
    }
}

// ---------------------------------------------------------------------------
extern "C" void kernel_launch(void* const* d_in, const int* in_sizes, int n_in,
                              void* d_out, int out_size)
{
    const float* x  = (const float*)d_in[0];
    const float* Wq = (const float*)d_in[1];
    const float* bq = (const float*)d_in[2];
    const float* Wk = (const float*)d_in[3];
    const float* bk = (const float*)d_in[4];
    const float* Wb = (const float*)d_in[5];
    const float* bb = (const float*)d_in[6];
    float* out = (float*)d_out;

    prep_kernel<<<1560, 256>>>(x, Wq, Wk);
    proj_mma_kernel<<<dim3(32, 6), 256>>>();
    combine_kernel<<<NTOK / 16, 256>>>(bq, bk, Wb, bb);
    pair_kernel<<<dim3(160, BB_), 256>>>(out);
}